// round 3
// baseline (speedup 1.0000x reference)
#include <cuda_runtime.h>

// Problem constants (fixed by the dataset: B=128, C=1024, N=512, NUM_CLASSES=1024)
#define BB 128
#define CC 1024
#define NN 512
#define NC 1024
#define MAXL 64   // max body-list entries per c; Binomial(512,0.02)*2 ~ 20 avg, <40 max

// ---- scratch (device globals; no allocation allowed) ----
__device__ float    g_mt[NN][BB];          // m transposed: m_t[n][b] = preds[b, atoms[n]]
__device__ int      g_body_list[CC][MAXL]; // packed (n<<1)|isNeg
__device__ int      g_body_cnt[CC];
__device__ int      g_head_map[CC];        // (n<<1)|isNeg, -1 if row empty
__device__ int      g_atom_inv[NC];        // class j -> atom index n, or -1
__device__ unsigned g_lb[BB * NN];         // bit-pattern fp max accumulators (nonneg floats)
__device__ unsigned g_ub[BB * NN];

// Kernel 1: build all sparse metadata + zero accumulators + gather m_t.
// grid = CC blocks of 128 threads. One float4 per thread per mask array.
__global__ void __launch_bounds__(128) k_build(
    const float* __restrict__ preds,
    const float* __restrict__ pos_head,
    const float* __restrict__ neg_head,
    const float* __restrict__ pos_body,
    const float* __restrict__ neg_body,
    const int* __restrict__ atoms)   // jax downcasts int64 -> int32
{
    const int c = blockIdx.x;
    const int t = threadIdx.x;
    const int gid = c * 128 + t;   // 0 .. 131071

    // Front-batch all independent loads: 4x float4 mask loads (MLP=4).
    const float4 p = ((const float4*)(pos_body + c * NN))[t];
    const float4 q = ((const float4*)(neg_body + c * NN))[t];
    const float4 h = ((const float4*)(pos_head + c * NN))[t];
    const float4 g = ((const float4*)(neg_head + c * NN))[t];

    // Zero lb/ub accumulators (first 512 CTAs cover all B*N = 65536)
    if (gid < BB * NN) {
        g_lb[gid] = 0u;
        g_ub[gid] = 0u;
    }

    // CTA 0 builds atom_inv (init -1, then scatter atoms). Block-uniform branch.
    if (c == 0) {
        for (int j = t; j < NC; j += 128) g_atom_inv[j] = -1;
        __syncthreads();
        for (int n = t; n < NN; n += 128) g_atom_inv[atoms[n] & (NC - 1)] = n;
    }

    // CTAs 0..511: gather transposed m. Thread t = batch b. (L2-resident preds)
    if (c < NN) {
        const int col = atoms[c] & (NC - 1);
        g_mt[c][t] = preds[t * NC + col];
    }

    __shared__ int cnt;
    __shared__ int headm;
    if (t == 0) { cnt = 0; headm = -1; }
    __syncthreads();

    // Compact this thread's 4 columns (n0..n0+3) into local buffer, then one atomic.
    const int n0 = t * 4;
    int local[8];
    int ln = 0;
    if (p.x > 0.5f) local[ln++] = ((n0 + 0) << 1);
    if (p.y > 0.5f) local[ln++] = ((n0 + 1) << 1);
    if (p.z > 0.5f) local[ln++] = ((n0 + 2) << 1);
    if (p.w > 0.5f) local[ln++] = ((n0 + 3) << 1);
    if (q.x > 0.5f) local[ln++] = ((n0 + 0) << 1) | 1;
    if (q.y > 0.5f) local[ln++] = ((n0 + 1) << 1) | 1;
    if (q.z > 0.5f) local[ln++] = ((n0 + 2) << 1) | 1;
    if (q.w > 0.5f) local[ln++] = ((n0 + 3) << 1) | 1;
    if (ln) {
        int base = atomicAdd(&cnt, ln);
        #pragma unroll
        for (int i = 0; i < 8; i++)
            if (i < ln && base + i < MAXL) g_body_list[c][base + i] = local[i];
    }

    // Head: exactly one nonzero across (ph row, nh row) -> plain write race-free.
    int hm = -1;
    if (h.x > 0.5f) hm = ((n0 + 0) << 1);
    if (h.y > 0.5f) hm = ((n0 + 1) << 1);
    if (h.z > 0.5f) hm = ((n0 + 2) << 1);
    if (h.w > 0.5f) hm = ((n0 + 3) << 1);
    if (g.x > 0.5f) hm = ((n0 + 0) << 1) | 1;
    if (g.y > 0.5f) hm = ((n0 + 1) << 1) | 1;
    if (g.z > 0.5f) hm = ((n0 + 2) << 1) | 1;
    if (g.w > 0.5f) hm = ((n0 + 3) << 1) | 1;
    if (hm >= 0) headm = hm;

    __syncthreads();
    if (t == 0) {
        g_body_cnt[c] = min(cnt, MAXL);
        g_head_map[c] = headm;
    }
}

// Kernel 2: body_min per (b,c) from the sparse list, then atomicMax-scatter
// into lb/ub via the single head entry of row c.
// grid = CC blocks, 128 threads (thread = b).
__global__ void __launch_bounds__(128) k_bodymin()
{
    const int c = blockIdx.x;
    const int b = threadIdx.x;

    const int cnt = g_body_cnt[c];      // uniform
    const int hm  = g_head_map[c];      // uniform

    // Dual accumulators: fmax over [0,1] values is associative/commutative -> exact.
    float a0 = 0.0f, a1 = 0.0f;
    int i = 0;
    #pragma unroll 2
    for (; i + 2 <= cnt; i += 2) {
        int e0 = g_body_list[c][i];
        int e1 = g_body_list[c][i + 1];
        float m0 = g_mt[(e0 >> 1) & (NN - 1)][b];
        float m1 = g_mt[(e1 >> 1) & (NN - 1)][b];
        float t0 = (e0 & 1) ? m0 : (1.0f - m0);
        float t1 = (e1 & 1) ? m1 : (1.0f - m1);
        a0 = fmaxf(a0, t0);
        a1 = fmaxf(a1, t1);
    }
    if (i < cnt) {
        int e = g_body_list[c][i];
        float m = g_mt[(e >> 1) & (NN - 1)][b];
        a0 = fmaxf(a0, (e & 1) ? m : (1.0f - m));
    }
    float bmin = 1.0f - fmaxf(a0, a1);  // same op order as reference (1 - max)

    if (hm >= 0) {
        const int n = (hm >> 1) & (NN - 1);
        const unsigned bits = __float_as_uint(bmin);  // bmin in [0,1] -> order-preserving
        if (hm & 1) atomicMax(&g_ub[b * NN + n], bits);
        else        atomicMax(&g_lb[b * NN + n], bits);
    }
}

// Kernel 3: write full output; atom columns get clamp(m, lo, hi). float4 over j.
__global__ void __launch_bounds__(256) k_out(const float* __restrict__ preds,
                                             float* __restrict__ out)
{
    const int vid = blockIdx.x * 256 + threadIdx.x;   // 0 .. 32767
    if (vid >= BB * NC / 4) return;
    const int b  = vid >> 8;          // / (NC/4)
    const int j0 = (vid & 255) * 4;   // column of first element

    float4 v = ((const float4*)preds)[vid];
    float* vp = (float*)&v;
    #pragma unroll
    for (int k = 0; k < 4; k++) {
        const int n = g_atom_inv[j0 + k];
        if (n >= 0) {
            float lb = __uint_as_float(g_lb[b * NN + n]);
            float ub = 1.0f - __uint_as_float(g_ub[b * NN + n]);
            float lo = fminf(lb, ub);
            float hi = fmaxf(lb, ub);
            vp[k] = fmaxf(lo, fminf(hi, vp[k]));
        }
    }
    ((float4*)out)[vid] = v;
}

extern "C" void kernel_launch(void* const* d_in, const int* in_sizes, int n_in,
                              void* d_out, int out_size)
{
    const float* preds    = (const float*)d_in[0];
    const float* pos_head = (const float*)d_in[1];
    const float* neg_head = (const float*)d_in[2];
    const float* pos_body = (const float*)d_in[3];
    const float* neg_body = (const float*)d_in[4];
    const int*   atoms    = (const int*)d_in[5];
    float* out = (float*)d_out;

    k_build<<<CC, 128>>>(preds, pos_head, neg_head, pos_body, neg_body, atoms);
    k_bodymin<<<CC, 128>>>();
    k_out<<<(BB * NC / 4 + 255) / 256, 256>>>(preds, out);
}

// round 4
// speedup vs baseline: 1.1800x; 1.1800x over previous
#include <cuda_runtime.h>

// Problem constants (fixed: B=128, C=1024, N=512, NUM_CLASSES=1024)
#define BB 128
#define CC 1024
#define NN 512
#define NC 1024
#define MAXL 64   // max body entries per row; Binomial(512,0.02)*2 ~ 20 avg, <45 max

// ---- scratch (device globals; zero-init at load; self-resetting counters) ----
__device__ float    g_mt[NN][BB];       // m transposed: m_t[n][b] = preds[b, atoms[n]]
__device__ int      g_head_map[CC];     // (n<<1)|isNeg for row c
__device__ int      g_inv_cnt[NN];      // #rows whose head is atom n (reset by finalizer)
__device__ int      g_done[NN];         // arrival counter per n (reset by finalizer)
__device__ unsigned g_lb[NN * BB];      // fp-bit max accumulators (nonneg floats)
__device__ unsigned g_ub[NN * BB];

// ============ Kernel A: prep ============
// grid = CC blocks x 128 threads. All parts independent -> front-batched loads.
__global__ void __launch_bounds__(128) k_prep(
    const float* __restrict__ preds,
    const float* __restrict__ pos_head,
    const float* __restrict__ neg_head,
    const int*   __restrict__ atoms,     // jax downcasts int64 -> int32
    float*       __restrict__ out)
{
    const int c = blockIdx.x;
    const int t = threadIdx.x;
    const int gid = c * 128 + t;        // 0 .. 131071

    // head-mask row loads (1 float4 each per thread)
    const float4 h = ((const float4*)(pos_head + c * NN))[t];
    const float4 g = ((const float4*)(neg_head + c * NN))[t];

    // copy preds -> out (32768 float4 over first 256 CTAs)
    if (gid < BB * NC / 4)
        ((float4*)out)[gid] = ((const float4*)preds)[gid];

    // zero lb/ub accumulators (65536 words each; first 512 CTAs)
    if (gid < NN * BB) { g_lb[gid] = 0u; g_ub[gid] = 0u; }

    // gather transposed m (CTAs 0..511, thread t = batch b)
    if (c < NN)
        g_mt[c][t] = preds[t * NC + (atoms[c] & (NC - 1))];

    // find the single head entry of row c (exactly one nonzero across h,g)
    const int n0 = t * 4;
    int hm = -1;
    if (h.x > 0.5f) hm = ((n0 + 0) << 1);
    if (h.y > 0.5f) hm = ((n0 + 1) << 1);
    if (h.z > 0.5f) hm = ((n0 + 2) << 1);
    if (h.w > 0.5f) hm = ((n0 + 3) << 1);
    if (g.x > 0.5f) hm = ((n0 + 0) << 1) | 1;
    if (g.y > 0.5f) hm = ((n0 + 1) << 1) | 1;
    if (g.z > 0.5f) hm = ((n0 + 2) << 1) | 1;
    if (g.w > 0.5f) hm = ((n0 + 3) << 1) | 1;
    if (hm >= 0) {                       // one finder thread per CTA
        g_head_map[c] = hm;
        atomicAdd(&g_inv_cnt[(hm >> 1) & (NN - 1)], 1);
    }
}

// ============ Kernel B: body_min + scatter + in-kernel finalize ============
// grid = CC blocks x 128 threads (thread = b). Perfectly balanced: 1 row per CTA.
// Last CTA to arrive for atom n writes the output column (release/acquire via
// threadfence + L2 atomics; L1 flushed per launch on sm_103a, volatile loads hit L2).
__global__ void __launch_bounds__(128) k_body(
    const float* __restrict__ pos_body,
    const float* __restrict__ neg_body,
    const int*   __restrict__ atoms,
    float*       __restrict__ out)
{
    const int c = blockIdx.x;
    const int t = threadIdx.x;

    // front-batch body-row loads
    const float4 p = ((const float4*)(pos_body + c * NN))[t];
    const float4 q = ((const float4*)(neg_body + c * NN))[t];
    const int hm = g_head_map[c];

    __shared__ int lcnt;
    __shared__ int lst[MAXL];
    __shared__ int s_last;
    if (t == 0) lcnt = 0;
    __syncthreads();

    // compact this thread's 4 columns into smem list (order irrelevant: exact max)
    const int n0 = t * 4;
    int loc[8]; int ln = 0;
    if (p.x > 0.5f) loc[ln++] = ((n0 + 0) << 1);
    if (p.y > 0.5f) loc[ln++] = ((n0 + 1) << 1);
    if (p.z > 0.5f) loc[ln++] = ((n0 + 2) << 1);
    if (p.w > 0.5f) loc[ln++] = ((n0 + 3) << 1);
    if (q.x > 0.5f) loc[ln++] = ((n0 + 0) << 1) | 1;
    if (q.y > 0.5f) loc[ln++] = ((n0 + 1) << 1) | 1;
    if (q.z > 0.5f) loc[ln++] = ((n0 + 2) << 1) | 1;
    if (q.w > 0.5f) loc[ln++] = ((n0 + 3) << 1) | 1;
    if (ln) {
        int base = atomicAdd(&lcnt, ln);
        #pragma unroll
        for (int i = 0; i < 8; i++)
            if (i < ln && base + i < MAXL) lst[base + i] = loc[i];
    }
    __syncthreads();

    // body max for batch b=t: dual accumulators (fmax exact/associative on [0,1])
    const int cnt = min(lcnt, MAXL);
    float a0 = 0.0f, a1 = 0.0f;
    int i = 0;
    for (; i + 2 <= cnt; i += 2) {
        int e0 = lst[i], e1 = lst[i + 1];
        float m0 = g_mt[(e0 >> 1) & (NN - 1)][t];
        float m1 = g_mt[(e1 >> 1) & (NN - 1)][t];
        a0 = fmaxf(a0, (e0 & 1) ? m0 : (1.0f - m0));
        a1 = fmaxf(a1, (e1 & 1) ? m1 : (1.0f - m1));
    }
    if (i < cnt) {
        int e = lst[i];
        float m = g_mt[(e >> 1) & (NN - 1)][t];
        a0 = fmaxf(a0, (e & 1) ? m : (1.0f - m));
    }
    const float bmin = 1.0f - fmaxf(a0, a1);   // same op order as reference

    // scatter: one atomicMax per (c,b) into lb or ub of head atom n
    const int n = (hm >> 1) & (NN - 1);
    const unsigned bits = __float_as_uint(bmin);  // bmin in (0,1] -> order-preserving
    if (hm >= 0) {
        if (hm & 1) atomicMax(&g_ub[n * BB + t], bits);
        else        atomicMax(&g_lb[n * BB + t], bits);
    }

    // release: make maxes visible, then arrive on n's done counter
    __threadfence();
    __syncthreads();
    if (t == 0)
        s_last = (hm >= 0) && (atomicAdd(&g_done[n], 1) == g_inv_cnt[n] - 1);
    __syncthreads();

    // last arriver for n finalizes the output column
    if (s_last) {
        __threadfence();  // acquire side
        unsigned lbits = *(volatile unsigned*)&g_lb[n * BB + t];
        unsigned ubits = *(volatile unsigned*)&g_ub[n * BB + t];
        float lb = __uint_as_float(lbits);
        float ub = 1.0f - __uint_as_float(ubits);
        float lo = fminf(lb, ub);
        float hi = fmaxf(lb, ub);
        float m  = g_mt[n][t];
        out[t * NC + (atoms[n] & (NC - 1))] = fmaxf(lo, fminf(hi, m));
        if (t == 0) { g_done[n] = 0; g_inv_cnt[n] = 0; }  // replay-safe reset
    }
}

extern "C" void kernel_launch(void* const* d_in, const int* in_sizes, int n_in,
                              void* d_out, int out_size)
{
    const float* preds    = (const float*)d_in[0];
    const float* pos_head = (const float*)d_in[1];
    const float* neg_head = (const float*)d_in[2];
    const float* pos_body = (const float*)d_in[3];
    const float* neg_body = (const float*)d_in[4];
    const int*   atoms    = (const int*)d_in[5];
    float* out = (float*)d_out;

    k_prep<<<CC, 128>>>(preds, pos_head, neg_head, atoms, out);
    k_body<<<CC, 128>>>(pos_body, neg_body, atoms, out);
}